// round 15
// baseline (speedup 1.0000x reference)
#include <cuda_runtime.h>
#include <cuda_bf16.h>
#include <cuda_fp16.h>
#include <math.h>
#include <float.h>
#include <stdint.h>

// Shapes (fixed by the problem)
#define NB  4
#define C   64
#define HH  128
#define HWD (128*128)   // 16384 full-res positions per batch
#define F   4096        // 64x64 pooled positions per batch
#define CQ  8           // query/key channels
#define CV  32          // value channels
#define TK  128         // queries per attn block (MMA M)
#define SFC 128         // f per stage in attn
#define VSTR 80         // v smem row stride bytes
#define LOG2E 1.4426950408889634f
#define PARTN ((size_t)NB*HWD*CV)

// ---------------- scratch (device globals) ----------------
__device__ float g_qf [NB*(HWD/8)*64];     // fragment-ordered q (tf32)
__device__ float g_kpf[NB*(F/8)*64];       // fragment-ordered kp*log2e (tf32)
__device__ float g_kpt[NB*CQ*F];           // [b][c][f] kp*log2e (stats persistent A)
__device__ float g_v  [NB*F*CV];           // [b][f][c] raw pooled v (fp32)
__device__ float g_z  [NB*F];              // Z[b][f] (atomic accum)
__device__ __half g_v16[NB*F*CV];          // [b][f][c] fp16 v
__device__ float g_part[2*NB*HWD*CV];      // [half][b*q][c] fp32 attn partials

// ---------------- PTX helpers ----------------
__device__ __forceinline__ uint32_t smem_u32(const void* p) {
    uint32_t a;
    asm("{ .reg .u64 t; cvta.to.shared.u64 t, %1; cvt.u32.u64 %0, t; }" : "=r"(a) : "l"(p));
    return a;
}
#define CVT_BF16X2_F32(res, a, b) \
    asm("cvt.rn.bf16x2.f32 %0, %1, %2;" : "=r"(res) : "f"(b), "f"(a))
#define CVT_F16X2_F32(res, a, b) \
    asm("cvt.rn.f16x2.f32 %0, %1, %2;" : "=r"(res) : "f"(b), "f"(a))
#define EX2F(d, s)   asm("ex2.approx.f32 %0, %1;" : "=f"(d) : "f"(s))
#define EX2H2(d, s)  asm("ex2.approx.f16x2 %0, %1;" : "=r"(d) : "r"(s))
#define LG2F(d, s)   asm("lg2.approx.f32 %0, %1;" : "=f"(d) : "f"(s))
#define TF32R(u, v)  asm("cvt.rna.tf32.f32 %0, %1;" : "=r"(u) : "f"(v))
#define LDS32(d, a)  asm volatile("ld.shared.b32 %0, [%1];" : "=r"(d) : "r"(a))
#define CP_ASYNC16(dst, src) \
    asm volatile("cp.async.ca.shared.global [%0], [%1], 16;" :: "r"(dst), "l"(src))
#define CP_COMMIT asm volatile("cp.async.commit_group;" ::: "memory")
#define CP_WAIT0  asm volatile("cp.async.wait_group 0;" ::: "memory")

__device__ __forceinline__ void ldmatrix_x4_trans(uint32_t& r0, uint32_t& r1,
                                                  uint32_t& r2, uint32_t& r3,
                                                  uint32_t addr) {
    asm volatile("ldmatrix.sync.aligned.m8n8.x4.trans.shared.b16 {%0,%1,%2,%3}, [%4];"
        : "=r"(r0), "=r"(r1), "=r"(r2), "=r"(r3) : "r"(addr));
}
__device__ __forceinline__ void mma16816bf(float* d, const uint32_t* a,
                                           uint32_t b0, uint32_t b1) {
    asm volatile(
      "mma.sync.aligned.m16n8k16.row.col.f32.bf16.bf16.f32 "
      "{%0,%1,%2,%3}, {%4,%5,%6,%7}, {%8,%9}, {%0,%1,%2,%3};"
      : "+f"(d[0]), "+f"(d[1]), "+f"(d[2]), "+f"(d[3])
      : "r"(a[0]), "r"(a[1]), "r"(a[2]), "r"(a[3]), "r"(b0), "r"(b1));
}
__device__ __forceinline__ void mma16816h(float* d, const uint32_t* a,
                                          uint32_t b0, uint32_t b1) {
    asm volatile(
      "mma.sync.aligned.m16n8k16.row.col.f32.f16.f16.f32 "
      "{%0,%1,%2,%3}, {%4,%5,%6,%7}, {%8,%9}, {%0,%1,%2,%3};"
      : "+f"(d[0]), "+f"(d[1]), "+f"(d[2]), "+f"(d[3])
      : "r"(a[0]), "r"(a[1]), "r"(a[2]), "r"(a[3]), "r"(b0), "r"(b1));
}
__device__ __forceinline__ void mma_tf32_c(float& d0, float& d1, float& d2, float& d3,
                                           uint32_t a0, uint32_t a1, uint32_t a2, uint32_t a3,
                                           uint32_t b0, uint32_t b1, float c0, float c1) {
    asm volatile(
      "mma.sync.aligned.m16n8k8.row.col.f32.tf32.tf32.f32 "
      "{%0,%1,%2,%3}, {%4,%5,%6,%7}, {%8,%9}, {%10,%11,%10,%11};"
      : "=f"(d0), "=f"(d1), "=f"(d2), "=f"(d3)
      : "r"(a0), "r"(a1), "r"(a2), "r"(a3), "r"(b0), "r"(b1),
        "f"(c0), "f"(c1));
}
__device__ __forceinline__ void mma_tf32_z(float& d0, float& d1, float& d2, float& d3,
                                           uint32_t a0, uint32_t a1, uint32_t a2, uint32_t a3,
                                           uint32_t b0, uint32_t b1) {
    mma_tf32_c(d0, d1, d2, d3, a0, a1, a2, a3, b0, b1, 0.f, 0.f);
}

// ---------------- K1: merged projections + 2x2 maxpool via shfl ----------------
__global__ __launch_bounds__(128) void k_proj(const float* __restrict__ x,
                                              const float* __restrict__ Wq,
                                              const float* __restrict__ Wk,
                                              const float* __restrict__ Wv) {
    __shared__ float wT[C][48];
    for (int i = threadIdx.x; i < C*48; i += 128) {
        int c = i / 48, j = i - c*48;
        float v;
        if (j < 8)       v = Wq[j*C + c];
        else if (j < 16) v = Wk[(j-8)*C + c];
        else             v = Wv[(j-16)*C + c];
        wT[c][j] = v;
    }
    __syncthreads();

    const int t = threadIdx.x;
    const int p = blockIdx.x*128 + t;
    const int cell = p >> 2;
    const int b = cell >> 12;
    const int f = cell & 4095;
    const int ph = f >> 6, pw = f & 63;
    const int h = 2*ph + ((t >> 1) & 1);
    const int w = 2*pw + (t & 1);
    const int hw = h*HH + w;
    const float* xp = x + (size_t)b*C*HWD + hw;

    float acc[48];
#pragma unroll
    for (int j = 0; j < 48; j++) acc[j] = 0.f;

#pragma unroll 4
    for (int c = 0; c < C; c++) {
        const float xv = __ldg(xp + c*HWD);
        const float4* wr = reinterpret_cast<const float4*>(&wT[c][0]);
#pragma unroll
        for (int j4 = 0; j4 < 12; j4++) {
            float4 ww = wr[j4];
            acc[4*j4+0] = fmaf(ww.x, xv, acc[4*j4+0]);
            acc[4*j4+1] = fmaf(ww.y, xv, acc[4*j4+1]);
            acc[4*j4+2] = fmaf(ww.z, xv, acc[4*j4+2]);
            acc[4*j4+3] = fmaf(ww.w, xv, acc[4*j4+3]);
        }
    }

    {
        float* qg = g_qf + ((size_t)(b*(HWD/8) + (hw >> 3)) << 6) + (hw & 7);
#pragma unroll
        for (int o = 0; o < CQ; o++) {
            uint32_t u; TF32R(u, acc[o]);
            qg[o*8] = __uint_as_float(u);
        }
    }

#pragma unroll
    for (int j = 8; j < 48; j++) {
        float m = acc[j];
        m = fmaxf(m, __shfl_xor_sync(0xffffffffu, m, 1));
        m = fmaxf(m, __shfl_xor_sync(0xffffffffu, m, 2));
        acc[j] = m;
    }
    if ((t & 3) == 0) {
        float* kg = g_kpf + ((size_t)(b*(F/8) + (f >> 3)) << 6) + (f & 7);
#pragma unroll
        for (int o = 0; o < CQ; o++) {
            uint32_t u; TF32R(u, acc[8+o] * LOG2E);
            float kv = __uint_as_float(u);
            kg[o*8] = kv;
            g_kpt[((b*CQ+o)<<12) + f] = kv;
        }
        float* vp = g_v + ((size_t)(b*F + f))*CV;
#pragma unroll
        for (int o = 0; o < CV; o++) vp[o] = acc[16+o];
        g_z[b*F + f] = 0.f;
    }
}

// ================= roles for the merged k_mix (all 128-thread) =================
#define STG 14848
#define KPOFF 10240
#define ZOFF  14336

// ---- attn role: f-split half; writes fp32 partials; log2(Z) computed in-stage
__device__ void attn_role(int b, int ablk, char* pool) {
    const uint32_t pb = smem_u32(pool);
    const int tid = threadIdx.x;
    const int w = tid >> 5, lane = tid & 31;
    const int g = lane >> 2, tg = lane & 3;
    const int half = ablk >> 7;
    const int kbase = (ablk & 127) * TK;
    const int frag = (tg*8 + g)*4;

    const int la0r = w*32 + g;
    const float* qf = g_qf + ((size_t)(b*(HWD/8)) << 6);
    uint32_t aq[2][4];
#pragma unroll
    for (int t = 0; t < 2; t++) {
        const int qa = kbase + la0r + t*16, qb = qa + 8;
        aq[t][0] = __float_as_uint(qf[((qa >> 3) << 6) + tg*8     + (qa & 7)]);
        aq[t][1] = __float_as_uint(qf[((qb >> 3) << 6) + tg*8     + (qb & 7)]);
        aq[t][2] = __float_as_uint(qf[((qa >> 3) << 6) + (tg+4)*8 + (qa & 7)]);
        aq[t][3] = __float_as_uint(qf[((qb >> 3) << 6) + (tg+4)*8 + (qb & 7)]);
    }

    const char* kpbat = reinterpret_cast<const char*>(g_kpf)
        + (((size_t)b*(F/8)) << 8) + (size_t)half*((F/2)/8)*256;
    const char* vbat  = reinterpret_cast<const char*>(g_v16)
        + (((size_t)b*F*CV) << 1) + (size_t)half*(F/2)*CV*2;
    const char* zbat  = reinterpret_cast<const char*>(g_z)
        + (((size_t)b*F) << 2) + (size_t)half*(F/2)*4;

    float acc[2][4][4];
#pragma unroll
    for (int t = 0; t < 2; t++)
#pragma unroll
        for (int i = 0; i < 4; i++)
#pragma unroll
            for (int j = 0; j < 4; j++) acc[t][i][j] = 0.f;

    // prologue
    {
#pragma unroll
        for (int k = 0; k < 4; k++) {
            int id = tid + k*128, row = id >> 2, seg = id & 3;
            CP_ASYNC16(pb + row*VSTR + seg*16, vbat + ((size_t)row << 6) + seg*16);
        }
#pragma unroll
        for (int k = 0; k < 2; k++) {
            int id = tid + k*128;
            CP_ASYNC16(pb + KPOFF + id*16, kpbat + id*16);
        }
        if (tid < 32) CP_ASYNC16(pb + ZOFF + tid*16, zbat + tid*16);
        CP_COMMIT;
    }

    const int NST = (F/2) / SFC;   // 16
    for (int st = 0; st < NST; st++) {
        CP_WAIT0;
        __syncthreads();
        // convert raw Z -> log2(Z) in place (128 entries, one per thread)
        {
            float* zbuf = reinterpret_cast<float*>(pool + (st & 1)*STG + ZOFF);
            float zlv; LG2F(zlv, zbuf[tid]);
            zbuf[tid] = zlv;
        }
        if (st + 1 < NST) {
            const uint32_t sb = pb + ((st+1) & 1)*STG;
            const char* vsrc = vbat + (((size_t)(st+1)*SFC*CV) << 1);
            const char* ksrc = kpbat + (((size_t)(st+1)*(SFC/8)) << 8);
            const char* zsrc = zbat + (((size_t)(st+1)*SFC) << 2);
#pragma unroll
            for (int k = 0; k < 4; k++) {
                int id = tid + k*128, row = id >> 2, seg = id & 3;
                CP_ASYNC16(sb + row*VSTR + seg*16, vsrc + ((size_t)row << 6) + seg*16);
            }
#pragma unroll
            for (int k = 0; k < 2; k++) {
                int id = tid + k*128;
                CP_ASYNC16(sb + KPOFF + id*16, ksrc + id*16);
            }
            if (tid < 32) CP_ASYNC16(sb + ZOFF + tid*16, zsrc + tid*16);
            CP_COMMIT;
        }
        __syncthreads();   // zl writes visible to all
        const uint32_t cb = pb + (st & 1)*STG;
        const uint32_t ldb = cb + (lane & 15)*VSTR + ((lane >> 4) & 1)*16;
        const uint32_t kpb = cb + KPOFF + frag;
        const float2* zlp = reinterpret_cast<const float2*>(
            pool + (st & 1)*STG + ZOFF);

#pragma unroll
        for (int tp = 0; tp < 8; tp++) {
            uint32_t A4[2][4];
#pragma unroll
            for (int h = 0; h < 2; h++) {
                const int gi = 2*tp + h;
                uint32_t kb0, kb1;
                LDS32(kb0, kpb + gi*256);
                LDS32(kb1, kpb + gi*256 + 128);
                const float2 zl2 = zlp[gi*4 + tg];
#pragma unroll
                for (int t = 0; t < 2; t++) {
                    float s0, s1, s2, s3;
                    mma_tf32_c(s0, s1, s2, s3,
                               aq[t][0], aq[t][1], aq[t][2], aq[t][3],
                               kb0, kb1, -zl2.x, -zl2.y);
                    uint32_t p0, p1;
                    CVT_F16X2_F32(p0, s0, s1);
                    CVT_F16X2_F32(p1, s2, s3);
                    EX2H2(A4[t][2*h],     p0);
                    EX2H2(A4[t][2*h + 1], p1);
                }
            }
            const uint32_t la0 = ldb + tp*16*VSTR;
            uint32_t b0, b1, b2, b3, b4, b5, b6, b7;
            ldmatrix_x4_trans(b0, b1, b2, b3, la0);
            ldmatrix_x4_trans(b4, b5, b6, b7, la0 + 32);
#pragma unroll
            for (int t = 0; t < 2; t++) {
                mma16816h(acc[t][0], A4[t], b0, b1);
                mma16816h(acc[t][1], A4[t], b2, b3);
                mma16816h(acc[t][2], A4[t], b4, b5);
                mma16816h(acc[t][3], A4[t], b6, b7);
            }
        }
    }

    __syncthreads();
    float (*out_s)[33] = reinterpret_cast<float(*)[33]>(pool);
#pragma unroll
    for (int t = 0; t < 2; t++) {
        const int lr = la0r + t*16;
#pragma unroll
        for (int nc = 0; nc < 4; nc++) {
            out_s[lr    ][nc*8 + tg*2    ] = acc[t][nc][0];
            out_s[lr    ][nc*8 + tg*2 + 1] = acc[t][nc][1];
            out_s[lr + 8][nc*8 + tg*2    ] = acc[t][nc][2];
            out_s[lr + 8][nc*8 + tg*2 + 1] = acc[t][nc][3];
        }
    }
    __syncthreads();

    float col[CV];
#pragma unroll
    for (int c = 0; c < CV; c++) col[c] = out_s[tid][c];
    float4* pp = reinterpret_cast<float4*>(
        g_part + (size_t)half*PARTN + (((size_t)(b << 14) + kbase + tid) << 5));
#pragma unroll
    for (int i = 0; i < 8; i++)
        pp[i] = make_float4(col[4*i], col[4*i+1], col[4*i+2], col[4*i+3]);
}

// ---- stats role (128 threads): partial Z via score-MMA + ones-MMA, atomicAdd
__device__ void stats_role(int b, int r, char* pool) {
    const int f0blk = (r >> 4) * 64;
    const int qsp = r & 15;
    const int tid = threadIdx.x;
    const int wf = tid >> 5, lane = tid & 31;
    const int g = lane >> 2, tg = lane & 3;
    const int fm = f0blk + wf*16;

    const float* kpt = g_kpt + ((size_t)(b*CQ) << 12);
    const uint32_t a0 = __float_as_uint(kpt[(tg    <<12) + fm + g    ]);
    const uint32_t a1 = __float_as_uint(kpt[(tg    <<12) + fm + g + 8]);
    const uint32_t a2 = __float_as_uint(kpt[((tg+4)<<12) + fm + g    ]);
    const uint32_t a3 = __float_as_uint(kpt[((tg+4)<<12) + fm + g + 8]);

    const float* qf = g_qf + ((size_t)(b*(HWD/8)) << 6);
    const int frag = tg*8 + g;
    const int qg0 = qsp*128;           // q-group base (1024 q per block)
    const uint32_t ONES = 0x3F803F80u;

    float z[4] = {0.f, 0.f, 0.f, 0.f};

    for (int st = 0; st < 16; st++) {
        const int gbase = qg0 + st*8;
#pragma unroll
        for (int tp = 0; tp < 4; tp++) {
            uint32_t A4[4];
#pragma unroll
            for (int h = 0; h < 2; h++) {
                const float* fp = qf + (((size_t)(gbase + 2*tp + h)) << 6) + frag;
                const uint32_t b0 = __float_as_uint(__ldg(fp));
                const uint32_t b1 = __float_as_uint(__ldg(fp + 32));
                float s0, s1, s2, s3;
                mma_tf32_z(s0, s1, s2, s3, a0, a1, a2, a3, b0, b1);
                float e0, e1, e2, e3;
                EX2F(e0, s0); EX2F(e1, s1); EX2F(e2, s2); EX2F(e3, s3);
                CVT_BF16X2_F32(A4[2*h],     e0, e1);
                CVT_BF16X2_F32(A4[2*h + 1], e2, e3);
            }
            mma16816bf(z, A4, ONES, ONES);
        }
    }

    float* zs = reinterpret_cast<float*>(pool);   // 64 floats
    if (tg == 0) {
        zs[wf*16 + g    ] = z[0];
        zs[wf*16 + g + 8] = z[2];
    }
    __syncthreads();
    if (tid < 64)
        atomicAdd(&g_z[b*F + f0blk + tid], zs[tid]);
}

// ---- combine role (128 threads): sum halves + Wo GEMV + gamma + residual
__device__ void comb_role(int b, int cblk, char* pool,
                          const float* __restrict__ x, const float* __restrict__ Wo,
                          const float* __restrict__ gamma, float* __restrict__ out) {
    float* wo_s = reinterpret_cast<float*>(pool);   // 8KB
    const int tid = threadIdx.x;
    for (int i = tid; i < C*CV; i += 128) wo_s[i] = Wo[i];
    __syncthreads();

    const int q = cblk*128 + tid;
    const size_t qi = ((size_t)b << 14) + q;
    const float4* p0 = reinterpret_cast<const float4*>(g_part + (qi << 5));
    const float4* p1 = reinterpret_cast<const float4*>(g_part + PARTN + (qi << 5));

    float col[CV];
#pragma unroll
    for (int i = 0; i < 8; i++) {
        float4 a = p0[i], bb = p1[i];
        col[4*i]   = a.x + bb.x;
        col[4*i+1] = a.y + bb.y;
        col[4*i+2] = a.z + bb.z;
        col[4*i+3] = a.w + bb.w;
    }
    const float gm = *gamma;
#pragma unroll 4
    for (int co = 0; co < C; co++) {
        float y = 0.f;
#pragma unroll
        for (int c = 0; c < CV; c++) y = fmaf(wo_s[co*CV + c], col[c], y);
        size_t oidx = ((size_t)(b*C + co) << 14) + q;
        out[oidx] = fmaf(gm, y, __ldg(x + oidx));
    }
}

// ---- v16 role (128 threads, 128 blocks over all batches): v fp32 -> fp16
__device__ void v16_role(int vblk) {
    const int fi = vblk*128 + threadIdx.x;    // over NB*F
    const float4* vp = reinterpret_cast<const float4*>(g_v + (size_t)fi*CV);
    uint32_t packed[16];
#pragma unroll
    for (int i = 0; i < 8; i++) {
        float4 t4 = vp[i];
        CVT_F16X2_F32(packed[2*i],     t4.x, t4.y);
        CVT_F16X2_F32(packed[2*i + 1], t4.z, t4.w);
    }
    uint4* up = reinterpret_cast<uint4*>(
        reinterpret_cast<char*>(g_v16) + ((size_t)fi*CV)*2);
    const uint4* ps = reinterpret_cast<const uint4*>(packed);
#pragma unroll
    for (int i = 0; i < 4; i++) up[i] = ps[i];
}

// ---- merged dispatcher: attn(b_attn) | stats(b_stats) | combine(b_comb) | v16
__global__ __launch_bounds__(128, 5) void k_mix(int b_attn, int b_stats, int b_comb,
                                                int do_v16,
                                                const float* __restrict__ x,
                                                const float* __restrict__ Wo,
                                                const float* __restrict__ gamma,
                                                float* __restrict__ out) {
    __shared__ __align__(16) char pool[2*STG];
    int blk = blockIdx.x;
    int n = (b_attn >= 0) ? 256 : 0;
    if (blk < n) { attn_role(b_attn, blk, pool); return; }
    blk -= n;
    n = (b_stats >= 0) ? 1024 : 0;
    if (blk < n) { stats_role(b_stats, blk, pool); return; }
    blk -= n;
    n = (b_comb >= 0) ? 128 : 0;
    if (blk < n) { comb_role(b_comb, blk, pool, x, Wo, gamma, out); return; }
    blk -= n;
    if (do_v16) v16_role(blk);
}

extern "C" void kernel_launch(void* const* d_in, const int* in_sizes, int n_in,
                              void* d_out, int out_size) {
    const float* x     = (const float*)d_in[0];
    const float* Wq    = (const float*)d_in[1];
    const float* Wk    = (const float*)d_in[2];
    const float* Wv    = (const float*)d_in[3];
    const float* Wo    = (const float*)d_in[4];
    const float* gamma = (const float*)d_in[5];
    float* out = (float*)d_out;

    // Single-stream software pipeline; overlap via merged grids (no streams —
    // stream creation allocates device memory and trips the harness guard).
    k_proj<<< NB*HWD/128, 128 >>>(x, Wq, Wk, Wv);
    k_mix<<< 1024 + 128, 128 >>>(-1, 0, -1, 1, x, Wo, gamma, out);   // stats(b0)+v16(all)
    k_mix<<<  256 + 1024, 128 >>>( 0, 1, -1, 0, x, Wo, gamma, out);  // attn(b0)+stats(b1)
    k_mix<<<  256 + 1024 + 128, 128 >>>( 1, 2, 0, 0, x, Wo, gamma, out);
    k_mix<<<  256 + 1024 + 128, 128 >>>( 2, 3, 1, 0, x, Wo, gamma, out);
    k_mix<<<  256 + 128, 128 >>>( 3, -1, 2, 0, x, Wo, gamma, out);   // attn(b3)+comb(b2)
    k_mix<<<  128, 128 >>>(-1, -1, 3, 0, x, Wo, gamma, out);         // comb(b3)
}

// round 16
// speedup vs baseline: 1.1189x; 1.1189x over previous
#include <cuda_runtime.h>
#include <cuda_bf16.h>
#include <cuda_fp16.h>
#include <math.h>
#include <float.h>
#include <stdint.h>

// Shapes (fixed by the problem)
#define NB  4
#define C   64
#define HH  128
#define HWD (128*128)   // 16384 full-res positions per batch
#define F   4096        // 64x64 pooled positions per batch
#define CQ  8           // query/key channels
#define CV  32          // value channels
#define TK  128         // queries per attn block (MMA M)
#define SFC 128         // f per stage in attn
#define VSTR 80         // v smem row stride bytes
#define LOG2E 1.4426950408889634f
#define PARTN ((size_t)NB*HWD*CV)

// ---------------- scratch (device globals) ----------------
__device__ float g_qf [NB*(HWD/8)*64];     // fragment-ordered q (tf32)
__device__ float g_kpf[NB*(F/8)*64];       // fragment-ordered kp*log2e (tf32)
__device__ float g_kpt[NB*CQ*F];           // [b][c][f] kp*log2e (stats persistent A)
__device__ float g_z  [NB*F];              // Z[b][f] (atomic accum)
__device__ __half g_v16[NB*F*CV];          // [b][f][c] fp16 v (written by proj)
__device__ float g_part[2*NB*HWD*CV];      // [half][b*q][c] fp32 attn partials

// ---------------- PTX helpers ----------------
__device__ __forceinline__ uint32_t smem_u32(const void* p) {
    uint32_t a;
    asm("{ .reg .u64 t; cvta.to.shared.u64 t, %1; cvt.u32.u64 %0, t; }" : "=r"(a) : "l"(p));
    return a;
}
#define CVT_BF16X2_F32(res, a, b) \
    asm("cvt.rn.bf16x2.f32 %0, %1, %2;" : "=r"(res) : "f"(b), "f"(a))
#define CVT_F16X2_F32(res, a, b) \
    asm("cvt.rn.f16x2.f32 %0, %1, %2;" : "=r"(res) : "f"(b), "f"(a))
#define EX2F(d, s)   asm("ex2.approx.f32 %0, %1;" : "=f"(d) : "f"(s))
#define EX2H2(d, s)  asm("ex2.approx.f16x2 %0, %1;" : "=r"(d) : "r"(s))
#define LG2F(d, s)   asm("lg2.approx.f32 %0, %1;" : "=f"(d) : "f"(s))
#define TF32R(u, v)  asm("cvt.rna.tf32.f32 %0, %1;" : "=r"(u) : "f"(v))
#define LDS32(d, a)  asm volatile("ld.shared.b32 %0, [%1];" : "=r"(d) : "r"(a))
#define CP_ASYNC16(dst, src) \
    asm volatile("cp.async.ca.shared.global [%0], [%1], 16;" :: "r"(dst), "l"(src))
#define CP_COMMIT asm volatile("cp.async.commit_group;" ::: "memory")
#define CP_WAIT0  asm volatile("cp.async.wait_group 0;" ::: "memory")

__device__ __forceinline__ void ldmatrix_x4_trans(uint32_t& r0, uint32_t& r1,
                                                  uint32_t& r2, uint32_t& r3,
                                                  uint32_t addr) {
    asm volatile("ldmatrix.sync.aligned.m8n8.x4.trans.shared.b16 {%0,%1,%2,%3}, [%4];"
        : "=r"(r0), "=r"(r1), "=r"(r2), "=r"(r3) : "r"(addr));
}
__device__ __forceinline__ void mma16816bf(float* d, const uint32_t* a,
                                           uint32_t b0, uint32_t b1) {
    asm volatile(
      "mma.sync.aligned.m16n8k16.row.col.f32.bf16.bf16.f32 "
      "{%0,%1,%2,%3}, {%4,%5,%6,%7}, {%8,%9}, {%0,%1,%2,%3};"
      : "+f"(d[0]), "+f"(d[1]), "+f"(d[2]), "+f"(d[3])
      : "r"(a[0]), "r"(a[1]), "r"(a[2]), "r"(a[3]), "r"(b0), "r"(b1));
}
__device__ __forceinline__ void mma16816h(float* d, const uint32_t* a,
                                          uint32_t b0, uint32_t b1) {
    asm volatile(
      "mma.sync.aligned.m16n8k16.row.col.f32.f16.f16.f32 "
      "{%0,%1,%2,%3}, {%4,%5,%6,%7}, {%8,%9}, {%0,%1,%2,%3};"
      : "+f"(d[0]), "+f"(d[1]), "+f"(d[2]), "+f"(d[3])
      : "r"(a[0]), "r"(a[1]), "r"(a[2]), "r"(a[3]), "r"(b0), "r"(b1));
}
__device__ __forceinline__ void mma_tf32_c(float& d0, float& d1, float& d2, float& d3,
                                           uint32_t a0, uint32_t a1, uint32_t a2, uint32_t a3,
                                           uint32_t b0, uint32_t b1, float c0, float c1) {
    asm volatile(
      "mma.sync.aligned.m16n8k8.row.col.f32.tf32.tf32.f32 "
      "{%0,%1,%2,%3}, {%4,%5,%6,%7}, {%8,%9}, {%10,%11,%10,%11};"
      : "=f"(d0), "=f"(d1), "=f"(d2), "=f"(d3)
      : "r"(a0), "r"(a1), "r"(a2), "r"(a3), "r"(b0), "r"(b1),
        "f"(c0), "f"(c1));
}
__device__ __forceinline__ void mma_tf32_z(float& d0, float& d1, float& d2, float& d3,
                                           uint32_t a0, uint32_t a1, uint32_t a2, uint32_t a3,
                                           uint32_t b0, uint32_t b1) {
    mma_tf32_c(d0, d1, d2, d3, a0, a1, a2, a3, b0, b1, 0.f, 0.f);
}

// ---------------- K1: projections + 2x2 maxpool; writes q-frags, kp, fp16 v ----
__global__ __launch_bounds__(128) void k_proj(const float* __restrict__ x,
                                              const float* __restrict__ Wq,
                                              const float* __restrict__ Wk,
                                              const float* __restrict__ Wv) {
    __shared__ float wT[C][48];
    for (int i = threadIdx.x; i < C*48; i += 128) {
        int c = i / 48, j = i - c*48;
        float v;
        if (j < 8)       v = Wq[j*C + c];
        else if (j < 16) v = Wk[(j-8)*C + c];
        else             v = Wv[(j-16)*C + c];
        wT[c][j] = v;
    }
    __syncthreads();

    const int t = threadIdx.x;
    const int p = blockIdx.x*128 + t;
    const int cell = p >> 2;
    const int b = cell >> 12;
    const int f = cell & 4095;
    const int ph = f >> 6, pw = f & 63;
    const int h = 2*ph + ((t >> 1) & 1);
    const int w = 2*pw + (t & 1);
    const int hw = h*HH + w;
    const float* xp = x + (size_t)b*C*HWD + hw;

    float acc[48];
#pragma unroll
    for (int j = 0; j < 48; j++) acc[j] = 0.f;

#pragma unroll 4
    for (int c = 0; c < C; c++) {
        const float xv = __ldg(xp + c*HWD);
        const float4* wr = reinterpret_cast<const float4*>(&wT[c][0]);
#pragma unroll
        for (int j4 = 0; j4 < 12; j4++) {
            float4 ww = wr[j4];
            acc[4*j4+0] = fmaf(ww.x, xv, acc[4*j4+0]);
            acc[4*j4+1] = fmaf(ww.y, xv, acc[4*j4+1]);
            acc[4*j4+2] = fmaf(ww.z, xv, acc[4*j4+2]);
            acc[4*j4+3] = fmaf(ww.w, xv, acc[4*j4+3]);
        }
    }

    {
        float* qg = g_qf + ((size_t)(b*(HWD/8) + (hw >> 3)) << 6) + (hw & 7);
#pragma unroll
        for (int o = 0; o < CQ; o++) {
            uint32_t u; TF32R(u, acc[o]);
            qg[o*8] = __uint_as_float(u);
        }
    }

#pragma unroll
    for (int j = 8; j < 48; j++) {
        float m = acc[j];
        m = fmaxf(m, __shfl_xor_sync(0xffffffffu, m, 1));
        m = fmaxf(m, __shfl_xor_sync(0xffffffffu, m, 2));
        acc[j] = m;
    }
    if ((t & 3) == 0) {
        float* kg = g_kpf + ((size_t)(b*(F/8) + (f >> 3)) << 6) + (f & 7);
#pragma unroll
        for (int o = 0; o < CQ; o++) {
            uint32_t u; TF32R(u, acc[8+o] * LOG2E);
            float kv = __uint_as_float(u);
            kg[o*8] = kv;
            g_kpt[((b*CQ+o)<<12) + f] = kv;
        }
        // fp16 v written directly (g_v fp32 eliminated)
        uint32_t packed[16];
#pragma unroll
        for (int i = 0; i < 16; i++)
            CVT_F16X2_F32(packed[i], acc[16 + 2*i], acc[16 + 2*i + 1]);
        uint4* up = reinterpret_cast<uint4*>(
            reinterpret_cast<char*>(g_v16) + (((size_t)(b*F + f))*CV << 1));
        const uint4* ps = reinterpret_cast<const uint4*>(packed);
#pragma unroll
        for (int i = 0; i < 4; i++) up[i] = ps[i];
        g_z[b*F + f] = 0.f;
    }
}

// ---------------- K2: partial Z via score-MMA + ones-MMA (pure MUFU exp) ------
__global__ __launch_bounds__(256) void k_stats_mma() {
    const int blk = blockIdx.x;
    const int b = blk >> 9;
    const int r = blk & 511;
    const int f0blk = (r >> 3) * 64;
    const int qsp = r & 7;
    const int tid = threadIdx.x;
    const int w = tid >> 5, lane = tid & 31;
    const int g = lane >> 2, tg = lane & 3;
    const int wf = w & 3, wq = w >> 2;
    const int fm = f0blk + wf*16;

    const float* kpt = g_kpt + ((size_t)(b*CQ) << 12);
    const uint32_t a0 = __float_as_uint(kpt[(tg    <<12) + fm + g    ]);
    const uint32_t a1 = __float_as_uint(kpt[(tg    <<12) + fm + g + 8]);
    const uint32_t a2 = __float_as_uint(kpt[((tg+4)<<12) + fm + g    ]);
    const uint32_t a3 = __float_as_uint(kpt[((tg+4)<<12) + fm + g + 8]);

    const float* qf = g_qf + ((size_t)(b*(HWD/8)) << 6);
    const int frag = tg*8 + g;
    const int qg0 = qsp*256 + wq*128;
    const uint32_t ONES = 0x3F803F80u;

    float z[4] = {0.f, 0.f, 0.f, 0.f};

    for (int st = 0; st < 16; st++) {
        const int gbase = qg0 + st*8;
#pragma unroll
        for (int tp = 0; tp < 4; tp++) {
            uint32_t A4[4];
#pragma unroll
            for (int h = 0; h < 2; h++) {
                const float* fp = qf + (((size_t)(gbase + 2*tp + h)) << 6) + frag;
                const uint32_t b0 = __float_as_uint(__ldg(fp));
                const uint32_t b1 = __float_as_uint(__ldg(fp + 32));
                float s0, s1, s2, s3;
                mma_tf32_z(s0, s1, s2, s3, a0, a1, a2, a3, b0, b1);
                float e0, e1, e2, e3;
                EX2F(e0, s0); EX2F(e1, s1); EX2F(e2, s2); EX2F(e3, s3);
                CVT_BF16X2_F32(A4[2*h],     e0, e1);
                CVT_BF16X2_F32(A4[2*h + 1], e2, e3);
            }
            mma16816bf(z, A4, ONES, ONES);
        }
    }

    __shared__ float zs[2][64];
    if (tg == 0) {
        zs[wq][wf*16 + g    ] = z[0];
        zs[wq][wf*16 + g + 8] = z[2];
    }
    __syncthreads();
    if (tid < 64)
        atomicAdd(&g_z[b*F + f0blk + tid], zs[0][tid] + zs[1][tid]);
}

// ---------------- K3: attention, f-split x2, in-stage log2(Z); fp32 partials ---
#define STG 14848
#define KPOFF 10240
#define ZOFF  14336
__global__ __launch_bounds__(128, 5) void k_attn_mma() {
    __shared__ __align__(16) char pool[2*STG];
    const uint32_t pb = smem_u32(pool);

    const int tid = threadIdx.x;
    const int w = tid >> 5, lane = tid & 31;
    const int g = lane >> 2, tg = lane & 3;
    const int b = blockIdx.y;
    const int half = blockIdx.z;
    const int kbase = blockIdx.x * TK;
    const int frag = (tg*8 + g)*4;

    const int la0r = w*32 + g;
    const float* qf = g_qf + ((size_t)(b*(HWD/8)) << 6);
    uint32_t aq[2][4];
#pragma unroll
    for (int t = 0; t < 2; t++) {
        const int qa = kbase + la0r + t*16, qb = qa + 8;
        aq[t][0] = __float_as_uint(qf[((qa >> 3) << 6) + tg*8     + (qa & 7)]);
        aq[t][1] = __float_as_uint(qf[((qb >> 3) << 6) + tg*8     + (qb & 7)]);
        aq[t][2] = __float_as_uint(qf[((qa >> 3) << 6) + (tg+4)*8 + (qa & 7)]);
        aq[t][3] = __float_as_uint(qf[((qb >> 3) << 6) + (tg+4)*8 + (qb & 7)]);
    }

    const char* kpbat = reinterpret_cast<const char*>(g_kpf)
        + (((size_t)b*(F/8)) << 8) + (size_t)half*((F/2)/8)*256;
    const char* vbat  = reinterpret_cast<const char*>(g_v16)
        + (((size_t)b*F*CV) << 1) + (size_t)half*(F/2)*CV*2;
    const char* zbat  = reinterpret_cast<const char*>(g_z)
        + (((size_t)b*F) << 2) + (size_t)half*(F/2)*4;

    float acc[2][4][4];
#pragma unroll
    for (int t = 0; t < 2; t++)
#pragma unroll
        for (int i = 0; i < 4; i++)
#pragma unroll
            for (int j = 0; j < 4; j++) acc[t][i][j] = 0.f;

    // prologue: stage 0
    {
#pragma unroll
        for (int k = 0; k < 4; k++) {
            int id = tid + k*128, row = id >> 2, seg = id & 3;
            CP_ASYNC16(pb + row*VSTR + seg*16, vbat + ((size_t)row << 6) + seg*16);
        }
#pragma unroll
        for (int k = 0; k < 2; k++) {
            int id = tid + k*128;
            CP_ASYNC16(pb + KPOFF + id*16, kpbat + id*16);
        }
        if (tid < 32) CP_ASYNC16(pb + ZOFF + tid*16, zbat + tid*16);
        CP_COMMIT;
    }

    const int NST = (F/2) / SFC;   // 16
    for (int st = 0; st < NST; st++) {
        CP_WAIT0;
        __syncthreads();
        // raw Z -> log2(Z) in place (128 entries, one per thread)
        {
            float* zbuf = reinterpret_cast<float*>(pool + (st & 1)*STG + ZOFF);
            float zlv; LG2F(zlv, zbuf[tid]);
            zbuf[tid] = zlv;
        }
        if (st + 1 < NST) {
            const uint32_t sb = pb + ((st+1) & 1)*STG;
            const char* vsrc = vbat + (((size_t)(st+1)*SFC*CV) << 1);
            const char* ksrc = kpbat + (((size_t)(st+1)*(SFC/8)) << 8);
            const char* zsrc = zbat + (((size_t)(st+1)*SFC) << 2);
#pragma unroll
            for (int k = 0; k < 4; k++) {
                int id = tid + k*128, row = id >> 2, seg = id & 3;
                CP_ASYNC16(sb + row*VSTR + seg*16, vsrc + ((size_t)row << 6) + seg*16);
            }
#pragma unroll
            for (int k = 0; k < 2; k++) {
                int id = tid + k*128;
                CP_ASYNC16(sb + KPOFF + id*16, ksrc + id*16);
            }
            if (tid < 32) CP_ASYNC16(sb + ZOFF + tid*16, zsrc + tid*16);
            CP_COMMIT;
        }
        __syncthreads();   // zl visible
        const uint32_t cb = pb + (st & 1)*STG;
        const uint32_t ldb = cb + (lane & 15)*VSTR + ((lane >> 4) & 1)*16;
        const uint32_t kpb = cb + KPOFF + frag;
        const float2* zlp = reinterpret_cast<const float2*>(
            pool + (st & 1)*STG + ZOFF);

#pragma unroll
        for (int tp = 0; tp < 8; tp++) {
            uint32_t A4[2][4];
#pragma unroll
            for (int h = 0; h < 2; h++) {
                const int gi = 2*tp + h;
                uint32_t kb0, kb1;
                LDS32(kb0, kpb + gi*256);
                LDS32(kb1, kpb + gi*256 + 128);
                const float2 zl2 = zlp[gi*4 + tg];
#pragma unroll
                for (int t = 0; t < 2; t++) {
                    float s0, s1, s2, s3;
                    mma_tf32_c(s0, s1, s2, s3,
                               aq[t][0], aq[t][1], aq[t][2], aq[t][3],
                               kb0, kb1, -zl2.x, -zl2.y);
                    uint32_t p0, p1;
                    CVT_F16X2_F32(p0, s0, s1);
                    CVT_F16X2_F32(p1, s2, s3);
                    EX2H2(A4[t][2*h],     p0);
                    EX2H2(A4[t][2*h + 1], p1);
                }
            }
            const uint32_t la0 = ldb + tp*16*VSTR;
            uint32_t b0, b1, b2, b3, b4, b5, b6, b7;
            ldmatrix_x4_trans(b0, b1, b2, b3, la0);
            ldmatrix_x4_trans(b4, b5, b6, b7, la0 + 32);
#pragma unroll
            for (int t = 0; t < 2; t++) {
                mma16816h(acc[t][0], A4[t], b0, b1);
                mma16816h(acc[t][1], A4[t], b2, b3);
                mma16816h(acc[t][2], A4[t], b4, b5);
                mma16816h(acc[t][3], A4[t], b6, b7);
            }
        }
    }

    __syncthreads();
    float (*out_s)[33] = reinterpret_cast<float(*)[33]>(pool);
#pragma unroll
    for (int t = 0; t < 2; t++) {
        const int lr = la0r + t*16;
#pragma unroll
        for (int nc = 0; nc < 4; nc++) {
            out_s[lr    ][nc*8 + tg*2    ] = acc[t][nc][0];
            out_s[lr    ][nc*8 + tg*2 + 1] = acc[t][nc][1];
            out_s[lr + 8][nc*8 + tg*2    ] = acc[t][nc][2];
            out_s[lr + 8][nc*8 + tg*2 + 1] = acc[t][nc][3];
        }
    }
    __syncthreads();

    float col[CV];
#pragma unroll
    for (int c = 0; c < CV; c++) col[c] = out_s[tid][c];
    float4* pp = reinterpret_cast<float4*>(
        g_part + (size_t)half*PARTN + (((size_t)(b << 14) + kbase + tid) << 5));
#pragma unroll
    for (int i = 0; i < 8; i++)
        pp[i] = make_float4(col[4*i], col[4*i+1], col[4*i+2], col[4*i+3]);
}

// ---------------- K4: combine halves + Wo GEMV + gamma + residual --------------
__global__ __launch_bounds__(256) void k_combine(const float* __restrict__ x,
                                                 const float* __restrict__ Wo,
                                                 const float* __restrict__ gamma,
                                                 float* __restrict__ out) {
    __shared__ float wo_s[C*CV];
    const int tid = threadIdx.x;
    for (int i = tid; i < C*CV; i += 256) wo_s[i] = Wo[i];
    __syncthreads();

    const int qi = blockIdx.x*256 + tid;       // global b*HWD + q
    const int b = qi >> 14, q = qi & (HWD-1);
    const float4* p0 = reinterpret_cast<const float4*>(g_part + ((size_t)qi << 5));
    const float4* p1 = reinterpret_cast<const float4*>(g_part + PARTN + ((size_t)qi << 5));

    float col[CV];
#pragma unroll
    for (int i = 0; i < 8; i++) {
        float4 a = p0[i], bb = p1[i];
        col[4*i]   = a.x + bb.x;
        col[4*i+1] = a.y + bb.y;
        col[4*i+2] = a.z + bb.z;
        col[4*i+3] = a.w + bb.w;
    }
    const float gm = *gamma;
#pragma unroll 4
    for (int co = 0; co < C; co++) {
        float y = 0.f;
#pragma unroll
        for (int c = 0; c < CV; c++) y = fmaf(wo_s[co*CV + c], col[c], y);
        size_t oidx = ((size_t)(b*C + co) << 14) + q;
        out[oidx] = fmaf(gm, y, __ldg(x + oidx));
    }
}

extern "C" void kernel_launch(void* const* d_in, const int* in_sizes, int n_in,
                              void* d_out, int out_size) {
    const float* x     = (const float*)d_in[0];
    const float* Wq    = (const float*)d_in[1];
    const float* Wk    = (const float*)d_in[2];
    const float* Wv    = (const float*)d_in[3];
    const float* Wo    = (const float*)d_in[4];
    const float* gamma = (const float*)d_in[5];
    float* out = (float*)d_out;

    k_proj      <<< NB*HWD/128, 128 >>> (x, Wq, Wk, Wv);
    k_stats_mma <<< NB*512, 256 >>> ();
    dim3 ga(HWD/TK, NB, 2);
    k_attn_mma  <<< ga, 128 >>> ();
    k_combine   <<< NB*HWD/256, 256 >>> (x, Wo, gamma, out);
}